// round 9
// baseline (speedup 1.0000x reference)
#include <cuda_runtime.h>
#include <cuda_bf16.h>
#include <stdint.h>

#define E       64
#define BLOCK   256
#define ITEMS   16
#define CHUNK   (BLOCK * ITEMS)   // 4096

// Scratch (no allocation allowed): supports up to B = 4096 blocks.
__device__ uint32_t g_counts[E * 4096];
__device__ uint32_t g_totals[E];

__device__ __forceinline__ uint32_t warp_incl_scan(uint32_t x, int lane) {
#pragma unroll
    for (int o = 1; o < 32; o <<= 1) {
        uint32_t y = __shfl_up_sync(0xffffffffu, x, o);
        if (lane >= o) x += y;
    }
    return x;
}

__global__ void k_zero() {
    if (threadIdx.x < E) g_totals[threadIdx.x] = 0u;
}

// ---------------------------------------------------------------------------
// K1: per-(expert, block) histogram, expert-major: g_counts[e*B + b]
// (R4 version: plain shared atomics — proven fast.)
// ---------------------------------------------------------------------------
__global__ __launch_bounds__(BLOCK) void k_hist(const int* __restrict__ experts, int B) {
    __shared__ uint32_t h[E];
    const int t = threadIdx.x;
    const int b = blockIdx.x;
    if (t < E) h[t] = 0u;
    __syncthreads();

    const int4* p = (const int4*)(experts + (size_t)b * CHUNK);
#pragma unroll
    for (int i = 0; i < CHUNK / (4 * BLOCK); i++) {     // 4 iterations
        int4 x = p[i * BLOCK + t];
        atomicAdd(&h[x.x], 1u);
        atomicAdd(&h[x.y], 1u);
        atomicAdd(&h[x.z], 1u);
        atomicAdd(&h[x.w], 1u);
    }
    __syncthreads();

    if (t < E) {
        uint32_t c = h[t];
        g_counts[(size_t)t * B + b] = c;
        atomicAdd(&g_totals[t], c);
    }
}

// ---------------------------------------------------------------------------
// K2: one block per expert. Seeds with exclusive scan of expert totals, then
// scans this expert's B per-block counts in place -> global start offsets.
// Also writes num_tokens_per_expert (float).
// ---------------------------------------------------------------------------
__global__ __launch_bounds__(256) void k_scan(int B, float* __restrict__ out_counts) {
    __shared__ uint32_t s_wsum[8];
    __shared__ uint32_t s_base;

    const int e = blockIdx.x;
    const int t = threadIdx.x;
    const int lane = t & 31, warp = t >> 5;

    if (t < 32) {
        uint32_t a = g_totals[t];
        uint32_t c = g_totals[t + 32];
        uint32_t contrib = (t < e ? a : 0u) + ((t + 32) < e ? c : 0u);
#pragma unroll
        for (int o = 16; o > 0; o >>= 1)
            contrib += __shfl_down_sync(0xffffffffu, contrib, o);
        if (t == 0) s_base = contrib;
    }
    if (t == 0) out_counts[e] = (float)g_totals[e];

    uint32_t* row = g_counts + (size_t)e * B;
    const int VB = B >> 8;               // 8 for B=2048
    uint32_t run = 0;
    uint32_t el[16];
#pragma unroll 8
    for (int k = 0; k < VB; k++) {
        uint32_t v = row[t * VB + k];
        el[k] = run;
        run += v;
    }

    uint32_t inc = warp_incl_scan(run, lane);
    if (lane == 31) s_wsum[warp] = inc;
    __syncthreads();
    if (t == 0) {
        uint32_t acc = 0;
#pragma unroll
        for (int w = 0; w < 8; w++) { uint32_t x = s_wsum[w]; s_wsum[w] = acc; acc += x; }
    }
    __syncthreads();

    uint32_t excl = inc - run + s_wsum[warp] + s_base;
#pragma unroll 8
    for (int k = 0; k < VB; k++)
        row[t * VB + k] = el[k] + excl;
}

// ---------------------------------------------------------------------------
// K3: stable scatter. R4 block radix-rank + smem OVERLAY:
//   Phase A: zero hist, blocked expert load, in-thread nibble ranks, counts.
//   Phase B: per-expert scans -> exclusive bases; delta vs global offsets.
//   Phase C: read per-item positions into registers (hist now dead).
//   Phase D: OVERLAY hist smem with s_val/s_meta; stage scores + packed meta.
//   Phase E: coalesced emit.
// ---------------------------------------------------------------------------
__global__ __launch_bounds__(BLOCK) void k_scatter(
    const float* __restrict__ scores,
    const int*   __restrict__ experts,
    float* __restrict__ out_scores,
    float* __restrict__ out_idx,
    int B)
{
    __shared__ uint32_t s_buf[2 * CHUNK];   // 32 KB overlay (hist | val+meta)
    __shared__ int      s_delta[E];
    __shared__ uint32_t s_lbase[E];

    uint16_t* hist   = (uint16_t*)s_buf;    // [E][BLOCK] counts -> excl prefix
    float*    s_val  = (float*)s_buf;       // words [0, CHUNK)
    uint32_t* s_meta = s_buf + CHUNK;       // words [CHUNK, 2*CHUNK)

    const int t = threadIdx.x;
    const int b = blockIdx.x;
    const int lane = t & 31, warp = t >> 5;

    // --- Phase A: zero hist (8 x STS.128) ---
    uint4 z4 = make_uint4(0u, 0u, 0u, 0u);
#pragma unroll
    for (int i = 0; i < 8; i++) ((uint4*)s_buf)[i * BLOCK + t] = z4;
    __syncthreads();

    // blocked expert load (4 x LDG.128, coalesced)
    int e[ITEMS];
    {
        const int4* ep = (const int4*)(experts + (size_t)b * CHUNK + t * ITEMS);
#pragma unroll
        for (int v = 0; v < 4; v++) {
            int4 x = ep[v];
            e[4 * v + 0] = x.x; e[4 * v + 1] = x.y;
            e[4 * v + 2] = x.z; e[4 * v + 3] = x.w;
        }
    }

    // in-thread stable rank (nibble-packed) + per-(expert,thread) count
    uint32_t rn0 = 0, rn1 = 0;
#pragma unroll
    for (int i = 0; i < ITEMS; i++) {
        int r = 0;
#pragma unroll
        for (int j = 0; j < i; j++) r += (e[j] == e[i]) ? 1 : 0;
        if (i < 8) rn0 |= (uint32_t)r << (4 * i);
        else       rn1 |= (uint32_t)r << (4 * (i - 8));
        hist[e[i] * BLOCK + t] = (uint16_t)(r + 1);
    }
    __syncthreads();

    // --- Phase B: per-expert exclusive scan over 256 thread counts ---
#pragma unroll
    for (int s = 0; s < E / 8; s++) {
        int ex = warp * (E / 8) + s;
        uint4 v = ((const uint4*)(hist + ex * BLOCK))[lane];   // 8 u16
        uint32_t w[4] = { v.x, v.y, v.z, v.w };
        uint32_t run = 0, el[8];
#pragma unroll
        for (int k = 0; k < 8; k++) {
            uint32_t c = (w[k >> 1] >> ((k & 1) * 16)) & 0xFFFFu;
            el[k] = run; run += c;
        }
        uint32_t inc = warp_incl_scan(run, lane);
        uint32_t excl = inc - run;
#pragma unroll
        for (int k = 0; k < 8; k++) el[k] += excl;
        uint4 o;
        o.x = el[0] | (el[1] << 16);
        o.y = el[2] | (el[3] << 16);
        o.z = el[4] | (el[5] << 16);
        o.w = el[6] | (el[7] << 16);
        ((uint4*)(hist + ex * BLOCK))[lane] = o;
        if (lane == 31) s_lbase[ex] = inc;   // row total (temp)
    }
    __syncthreads();

    // warp 0: block-local expert bases + delta vs scanned global offsets
    if (warp == 0) {
        uint32_t t0 = s_lbase[lane];
        uint32_t t1 = s_lbase[lane + 32];
        uint32_t i0 = warp_incl_scan(t0, lane);
        uint32_t tot0 = __shfl_sync(0xffffffffu, i0, 31);
        uint32_t e0 = i0 - t0;
        uint32_t i1 = warp_incl_scan(t1, lane);
        uint32_t e1 = i1 - t1 + tot0;
        uint32_t gb0 = g_counts[(size_t)lane * B + b];
        uint32_t gb1 = g_counts[(size_t)(lane + 32) * B + b];
        s_lbase[lane]       = e0;
        s_lbase[lane + 32]  = e1;
        s_delta[lane]       = (int)gb0 - (int)e0;
        s_delta[lane + 32]  = (int)gb1 - (int)e1;
    }
    __syncthreads();

    // --- Phase C: per-item local positions into registers (u16-packed) ---
    uint32_t p16[ITEMS / 2];
#pragma unroll
    for (int i = 0; i < ITEMS; i++) {
        uint32_t r = (i < 8) ? ((rn0 >> (4 * i)) & 0xFu)
                             : ((rn1 >> (4 * (i - 8))) & 0xFu);
        uint32_t p = s_lbase[e[i]] + (uint32_t)hist[e[i] * BLOCK + t] + r;
        if (i & 1) p16[i >> 1] |= p << 16;
        else       p16[i >> 1]  = p;
    }
    __syncthreads();   // all hist reads done -> safe to overlay

    // --- Phase D: stage scores + packed meta into sorted order ---
    {
        const float4* sp = (const float4*)(scores + (size_t)b * CHUNK + t * ITEMS);
#pragma unroll
        for (int v = 0; v < 4; v++) {
            float4 x = sp[v];
            float vv[4] = { x.x, x.y, x.z, x.w };
#pragma unroll
            for (int j = 0; j < 4; j++) {
                int i = 4 * v + j;
                uint32_t p = (p16[i >> 1] >> ((i & 1) * 16)) & 0xFFFFu;
                s_val[p]  = vv[j];
                s_meta[p] = (uint32_t)(t * ITEMS + i) | ((uint32_t)e[i] << 12);
            }
        }
    }
    __syncthreads();

    // --- Phase E: coalesced emit ---
    const int chunk_base = b * CHUNK;
#pragma unroll
    for (int i = 0; i < ITEMS; i++) {
        int p = t + i * BLOCK;
        float v = s_val[p];
        uint32_t m = s_meta[p];
        int li = (int)(m & 0xFFFu);
        int ei = (int)(m >> 12);
        int gp = p + s_delta[ei];
        out_scores[gp] = v;
        out_idx[gp]    = (float)(chunk_base + li);
    }
}

// ---------------------------------------------------------------------------
extern "C" void kernel_launch(void* const* d_in, const int* in_sizes, int n_in,
                              void* d_out, int out_size) {
    const float* scores  = (const float*)d_in[0];
    const int*   experts = (const int*)d_in[1];
    const int N = in_sizes[0];            // 8,388,608
    const int B = N / CHUNK;              // 2048

    float* out        = (float*)d_out;
    float* out_scores = out;
    float* out_idx    = out + N;
    float* out_counts = out + 2 * (size_t)N;

    k_zero<<<1, 64>>>();
    k_hist<<<B, BLOCK>>>(experts, B);
    k_scan<<<E, 256>>>(B, out_counts);
    k_scatter<<<B, BLOCK>>>(scores, experts, out_scores, out_idx, B);
}

// round 10
// speedup vs baseline: 1.0036x; 1.0036x over previous
#include <cuda_runtime.h>
#include <cuda_bf16.h>
#include <stdint.h>

#define E       64
#define BLOCK   256
#define ITEMS   16
#define CHUNK   (BLOCK * ITEMS)   // 4096

// Scratch (no allocation allowed): supports up to B = 4096 blocks.
__device__ uint32_t g_counts[E * 4096];
__device__ uint32_t g_totals[E];

__device__ __forceinline__ uint32_t warp_incl_scan(uint32_t x, int lane) {
#pragma unroll
    for (int o = 1; o < 32; o <<= 1) {
        uint32_t y = __shfl_up_sync(0xffffffffu, x, o);
        if (lane >= o) x += y;
    }
    return x;
}

__global__ void k_zero() {
    if (threadIdx.x < E) g_totals[threadIdx.x] = 0u;
}

// ---------------------------------------------------------------------------
// K1: per-(expert, block) histogram, expert-major: g_counts[e*B + b]
// (R4 version: plain shared atomics — proven fast.)
// ---------------------------------------------------------------------------
__global__ __launch_bounds__(BLOCK) void k_hist(const int* __restrict__ experts, int B) {
    __shared__ uint32_t h[E];
    const int t = threadIdx.x;
    const int b = blockIdx.x;
    if (t < E) h[t] = 0u;
    __syncthreads();

    const int4* p = (const int4*)(experts + (size_t)b * CHUNK);
#pragma unroll
    for (int i = 0; i < CHUNK / (4 * BLOCK); i++) {     // 4 iterations
        int4 x = p[i * BLOCK + t];
        atomicAdd(&h[x.x], 1u);
        atomicAdd(&h[x.y], 1u);
        atomicAdd(&h[x.z], 1u);
        atomicAdd(&h[x.w], 1u);
    }
    __syncthreads();

    if (t < E) {
        uint32_t c = h[t];
        g_counts[(size_t)t * B + b] = c;
        atomicAdd(&g_totals[t], c);
    }
}

// ---------------------------------------------------------------------------
// K2: one block per expert. Seeds with exclusive scan of expert totals, then
// scans this expert's B per-block counts in place -> global start offsets.
// Also writes num_tokens_per_expert (float).
// ---------------------------------------------------------------------------
__global__ __launch_bounds__(256) void k_scan(int B, float* __restrict__ out_counts) {
    __shared__ uint32_t s_wsum[8];
    __shared__ uint32_t s_base;

    const int e = blockIdx.x;
    const int t = threadIdx.x;
    const int lane = t & 31, warp = t >> 5;

    if (t < 32) {
        uint32_t a = g_totals[t];
        uint32_t c = g_totals[t + 32];
        uint32_t contrib = (t < e ? a : 0u) + ((t + 32) < e ? c : 0u);
#pragma unroll
        for (int o = 16; o > 0; o >>= 1)
            contrib += __shfl_down_sync(0xffffffffu, contrib, o);
        if (t == 0) s_base = contrib;
    }
    if (t == 0) out_counts[e] = (float)g_totals[e];

    uint32_t* row = g_counts + (size_t)e * B;
    const int VB = B >> 8;               // 8 for B=2048
    uint32_t run = 0;
    uint32_t el[16];
#pragma unroll 8
    for (int k = 0; k < VB; k++) {
        uint32_t v = row[t * VB + k];
        el[k] = run;
        run += v;
    }

    uint32_t inc = warp_incl_scan(run, lane);
    if (lane == 31) s_wsum[warp] = inc;
    __syncthreads();
    if (t == 0) {
        uint32_t acc = 0;
#pragma unroll
        for (int w = 0; w < 8; w++) { uint32_t x = s_wsum[w]; s_wsum[w] = acc; acc += x; }
    }
    __syncthreads();

    uint32_t excl = inc - run + s_wsum[warp] + s_base;
#pragma unroll 8
    for (int k = 0; k < VB; k++)
        row[t * VB + k] = el[k] + excl;
}

// ---------------------------------------------------------------------------
// K3: stable scatter. R4 block radix-rank + smem OVERLAY:
//   Phase A: zero hist, blocked expert load, in-thread nibble ranks, counts.
//   Phase B: per-expert scans -> exclusive bases; delta vs global offsets.
//   Phase C: read per-item positions into registers (hist now dead).
//   Phase D: OVERLAY hist smem with s_val/s_meta; stage scores + packed meta.
//   Phase E: coalesced emit.
// ---------------------------------------------------------------------------
__global__ __launch_bounds__(BLOCK) void k_scatter(
    const float* __restrict__ scores,
    const int*   __restrict__ experts,
    float* __restrict__ out_scores,
    float* __restrict__ out_idx,
    int B)
{
    __shared__ uint32_t s_buf[2 * CHUNK];   // 32 KB overlay (hist | val+meta)
    __shared__ int      s_delta[E];
    __shared__ uint32_t s_lbase[E];

    uint16_t* hist   = (uint16_t*)s_buf;    // [E][BLOCK] counts -> excl prefix
    float*    s_val  = (float*)s_buf;       // words [0, CHUNK)
    uint32_t* s_meta = s_buf + CHUNK;       // words [CHUNK, 2*CHUNK)

    const int t = threadIdx.x;
    const int b = blockIdx.x;
    const int lane = t & 31, warp = t >> 5;

    // --- Phase A: zero hist (8 x STS.128) ---
    uint4 z4 = make_uint4(0u, 0u, 0u, 0u);
#pragma unroll
    for (int i = 0; i < 8; i++) ((uint4*)s_buf)[i * BLOCK + t] = z4;
    __syncthreads();

    // blocked expert load (4 x LDG.128, coalesced)
    int e[ITEMS];
    {
        const int4* ep = (const int4*)(experts + (size_t)b * CHUNK + t * ITEMS);
#pragma unroll
        for (int v = 0; v < 4; v++) {
            int4 x = ep[v];
            e[4 * v + 0] = x.x; e[4 * v + 1] = x.y;
            e[4 * v + 2] = x.z; e[4 * v + 3] = x.w;
        }
    }

    // in-thread stable rank (nibble-packed) + per-(expert,thread) count
    uint32_t rn0 = 0, rn1 = 0;
#pragma unroll
    for (int i = 0; i < ITEMS; i++) {
        int r = 0;
#pragma unroll
        for (int j = 0; j < i; j++) r += (e[j] == e[i]) ? 1 : 0;
        if (i < 8) rn0 |= (uint32_t)r << (4 * i);
        else       rn1 |= (uint32_t)r << (4 * (i - 8));
        hist[e[i] * BLOCK + t] = (uint16_t)(r + 1);
    }
    __syncthreads();

    // --- Phase B: per-expert exclusive scan over 256 thread counts ---
#pragma unroll
    for (int s = 0; s < E / 8; s++) {
        int ex = warp * (E / 8) + s;
        uint4 v = ((const uint4*)(hist + ex * BLOCK))[lane];   // 8 u16
        uint32_t w[4] = { v.x, v.y, v.z, v.w };
        uint32_t run = 0, el[8];
#pragma unroll
        for (int k = 0; k < 8; k++) {
            uint32_t c = (w[k >> 1] >> ((k & 1) * 16)) & 0xFFFFu;
            el[k] = run; run += c;
        }
        uint32_t inc = warp_incl_scan(run, lane);
        uint32_t excl = inc - run;
#pragma unroll
        for (int k = 0; k < 8; k++) el[k] += excl;
        uint4 o;
        o.x = el[0] | (el[1] << 16);
        o.y = el[2] | (el[3] << 16);
        o.z = el[4] | (el[5] << 16);
        o.w = el[6] | (el[7] << 16);
        ((uint4*)(hist + ex * BLOCK))[lane] = o;
        if (lane == 31) s_lbase[ex] = inc;   // row total (temp)
    }
    __syncthreads();

    // warp 0: block-local expert bases + delta vs scanned global offsets
    if (warp == 0) {
        uint32_t t0 = s_lbase[lane];
        uint32_t t1 = s_lbase[lane + 32];
        uint32_t i0 = warp_incl_scan(t0, lane);
        uint32_t tot0 = __shfl_sync(0xffffffffu, i0, 31);
        uint32_t e0 = i0 - t0;
        uint32_t i1 = warp_incl_scan(t1, lane);
        uint32_t e1 = i1 - t1 + tot0;
        uint32_t gb0 = g_counts[(size_t)lane * B + b];
        uint32_t gb1 = g_counts[(size_t)(lane + 32) * B + b];
        s_lbase[lane]       = e0;
        s_lbase[lane + 32]  = e1;
        s_delta[lane]       = (int)gb0 - (int)e0;
        s_delta[lane + 32]  = (int)gb1 - (int)e1;
    }
    __syncthreads();

    // --- Phase C: per-item local positions into registers (u16-packed) ---
    uint32_t p16[ITEMS / 2];
#pragma unroll
    for (int i = 0; i < ITEMS; i++) {
        uint32_t r = (i < 8) ? ((rn0 >> (4 * i)) & 0xFu)
                             : ((rn1 >> (4 * (i - 8))) & 0xFu);
        uint32_t p = s_lbase[e[i]] + (uint32_t)hist[e[i] * BLOCK + t] + r;
        if (i & 1) p16[i >> 1] |= p << 16;
        else       p16[i >> 1]  = p;
    }
    __syncthreads();   // all hist reads done -> safe to overlay

    // --- Phase D: stage scores + packed meta into sorted order ---
    {
        const float4* sp = (const float4*)(scores + (size_t)b * CHUNK + t * ITEMS);
#pragma unroll
        for (int v = 0; v < 4; v++) {
            float4 x = sp[v];
            float vv[4] = { x.x, x.y, x.z, x.w };
#pragma unroll
            for (int j = 0; j < 4; j++) {
                int i = 4 * v + j;
                uint32_t p = (p16[i >> 1] >> ((i & 1) * 16)) & 0xFFFFu;
                s_val[p]  = vv[j];
                s_meta[p] = (uint32_t)(t * ITEMS + i) | ((uint32_t)e[i] << 12);
            }
        }
    }
    __syncthreads();

    // --- Phase E: coalesced emit ---
    const int chunk_base = b * CHUNK;
#pragma unroll
    for (int i = 0; i < ITEMS; i++) {
        int p = t + i * BLOCK;
        float v = s_val[p];
        uint32_t m = s_meta[p];
        int li = (int)(m & 0xFFFu);
        int ei = (int)(m >> 12);
        int gp = p + s_delta[ei];
        out_scores[gp] = v;
        out_idx[gp]    = (float)(chunk_base + li);
    }
}

// ---------------------------------------------------------------------------
extern "C" void kernel_launch(void* const* d_in, const int* in_sizes, int n_in,
                              void* d_out, int out_size) {
    const float* scores  = (const float*)d_in[0];
    const int*   experts = (const int*)d_in[1];
    const int N = in_sizes[0];            // 8,388,608
    const int B = N / CHUNK;              // 2048

    float* out        = (float*)d_out;
    float* out_scores = out;
    float* out_idx    = out + N;
    float* out_counts = out + 2 * (size_t)N;

    k_zero<<<1, 64>>>();
    k_hist<<<B, BLOCK>>>(experts, B);
    k_scan<<<E, 256>>>(B, out_counts);
    k_scatter<<<B, BLOCK>>>(scores, experts, out_scores, out_idx, B);
}

// round 11
// speedup vs baseline: 1.0099x; 1.0062x over previous
#include <cuda_runtime.h>
#include <cuda_bf16.h>
#include <stdint.h>

#define E       64
#define BLOCK   256
#define ITEMS   16
#define CHUNK   (BLOCK * ITEMS)   // 4096

// Scratch (no allocation allowed): supports up to B = 4096 blocks.
__device__ uint32_t g_counts[E * 4096];
__device__ uint32_t g_totals[E];

__device__ __forceinline__ uint32_t warp_incl_scan(uint32_t x, int lane) {
#pragma unroll
    for (int o = 1; o < 32; o <<= 1) {
        uint32_t y = __shfl_up_sync(0xffffffffu, x, o);
        if (lane >= o) x += y;
    }
    return x;
}

__global__ void k_zero() {
    if (threadIdx.x < E) g_totals[threadIdx.x] = 0u;
}

// ---------------------------------------------------------------------------
// K1: per-(expert, block) histogram, expert-major: g_counts[e*B + b]
// (R4 version: plain shared atomics — proven fast.)
// ---------------------------------------------------------------------------
__global__ __launch_bounds__(BLOCK) void k_hist(const int* __restrict__ experts, int B) {
    __shared__ uint32_t h[E];
    const int t = threadIdx.x;
    const int b = blockIdx.x;
    if (t < E) h[t] = 0u;
    __syncthreads();

    const int4* p = (const int4*)(experts + (size_t)b * CHUNK);
#pragma unroll
    for (int i = 0; i < CHUNK / (4 * BLOCK); i++) {     // 4 iterations
        int4 x = p[i * BLOCK + t];
        atomicAdd(&h[x.x], 1u);
        atomicAdd(&h[x.y], 1u);
        atomicAdd(&h[x.z], 1u);
        atomicAdd(&h[x.w], 1u);
    }
    __syncthreads();

    if (t < E) {
        uint32_t c = h[t];
        g_counts[(size_t)t * B + b] = c;
        atomicAdd(&g_totals[t], c);
    }
}

// ---------------------------------------------------------------------------
// K2: one block per expert. Seeds with exclusive scan of expert totals, then
// scans this expert's B per-block counts in place -> global start offsets.
// Also writes num_tokens_per_expert (float).
// ---------------------------------------------------------------------------
__global__ __launch_bounds__(256) void k_scan(int B, float* __restrict__ out_counts) {
    __shared__ uint32_t s_wsum[8];
    __shared__ uint32_t s_base;

    const int e = blockIdx.x;
    const int t = threadIdx.x;
    const int lane = t & 31, warp = t >> 5;

    if (t < 32) {
        uint32_t a = g_totals[t];
        uint32_t c = g_totals[t + 32];
        uint32_t contrib = (t < e ? a : 0u) + ((t + 32) < e ? c : 0u);
#pragma unroll
        for (int o = 16; o > 0; o >>= 1)
            contrib += __shfl_down_sync(0xffffffffu, contrib, o);
        if (t == 0) s_base = contrib;
    }
    if (t == 0) out_counts[e] = (float)g_totals[e];

    uint32_t* row = g_counts + (size_t)e * B;
    const int VB = B >> 8;               // 8 for B=2048
    uint32_t run = 0;
    uint32_t el[16];
#pragma unroll 8
    for (int k = 0; k < VB; k++) {
        uint32_t v = row[t * VB + k];
        el[k] = run;
        run += v;
    }

    uint32_t inc = warp_incl_scan(run, lane);
    if (lane == 31) s_wsum[warp] = inc;
    __syncthreads();
    if (t == 0) {
        uint32_t acc = 0;
#pragma unroll
        for (int w = 0; w < 8; w++) { uint32_t x = s_wsum[w]; s_wsum[w] = acc; acc += x; }
    }
    __syncthreads();

    uint32_t excl = inc - run + s_wsum[warp] + s_base;
#pragma unroll 8
    for (int k = 0; k < VB; k++)
        row[t * VB + k] = el[k] + excl;
}

// ---------------------------------------------------------------------------
// K3: stable scatter. R4 block radix-rank + smem OVERLAY:
//   Phase A: zero hist, blocked expert load, in-thread nibble ranks, counts.
//   Phase B: per-expert scans -> exclusive bases; delta vs global offsets.
//   Phase C: read per-item positions into registers (hist now dead).
//   Phase D: OVERLAY hist smem with s_val/s_meta; stage scores + packed meta.
//   Phase E: coalesced emit.
// ---------------------------------------------------------------------------
__global__ __launch_bounds__(BLOCK) void k_scatter(
    const float* __restrict__ scores,
    const int*   __restrict__ experts,
    float* __restrict__ out_scores,
    float* __restrict__ out_idx,
    int B)
{
    __shared__ uint32_t s_buf[2 * CHUNK];   // 32 KB overlay (hist | val+meta)
    __shared__ int      s_delta[E];
    __shared__ uint32_t s_lbase[E];

    uint16_t* hist   = (uint16_t*)s_buf;    // [E][BLOCK] counts -> excl prefix
    float*    s_val  = (float*)s_buf;       // words [0, CHUNK)
    uint32_t* s_meta = s_buf + CHUNK;       // words [CHUNK, 2*CHUNK)

    const int t = threadIdx.x;
    const int b = blockIdx.x;
    const int lane = t & 31, warp = t >> 5;

    // --- Phase A: zero hist (8 x STS.128) ---
    uint4 z4 = make_uint4(0u, 0u, 0u, 0u);
#pragma unroll
    for (int i = 0; i < 8; i++) ((uint4*)s_buf)[i * BLOCK + t] = z4;
    __syncthreads();

    // blocked expert load (4 x LDG.128, coalesced)
    int e[ITEMS];
    {
        const int4* ep = (const int4*)(experts + (size_t)b * CHUNK + t * ITEMS);
#pragma unroll
        for (int v = 0; v < 4; v++) {
            int4 x = ep[v];
            e[4 * v + 0] = x.x; e[4 * v + 1] = x.y;
            e[4 * v + 2] = x.z; e[4 * v + 3] = x.w;
        }
    }

    // in-thread stable rank (nibble-packed) + per-(expert,thread) count
    uint32_t rn0 = 0, rn1 = 0;
#pragma unroll
    for (int i = 0; i < ITEMS; i++) {
        int r = 0;
#pragma unroll
        for (int j = 0; j < i; j++) r += (e[j] == e[i]) ? 1 : 0;
        if (i < 8) rn0 |= (uint32_t)r << (4 * i);
        else       rn1 |= (uint32_t)r << (4 * (i - 8));
        hist[e[i] * BLOCK + t] = (uint16_t)(r + 1);
    }
    __syncthreads();

    // --- Phase B: per-expert exclusive scan over 256 thread counts ---
#pragma unroll
    for (int s = 0; s < E / 8; s++) {
        int ex = warp * (E / 8) + s;
        uint4 v = ((const uint4*)(hist + ex * BLOCK))[lane];   // 8 u16
        uint32_t w[4] = { v.x, v.y, v.z, v.w };
        uint32_t run = 0, el[8];
#pragma unroll
        for (int k = 0; k < 8; k++) {
            uint32_t c = (w[k >> 1] >> ((k & 1) * 16)) & 0xFFFFu;
            el[k] = run; run += c;
        }
        uint32_t inc = warp_incl_scan(run, lane);
        uint32_t excl = inc - run;
#pragma unroll
        for (int k = 0; k < 8; k++) el[k] += excl;
        uint4 o;
        o.x = el[0] | (el[1] << 16);
        o.y = el[2] | (el[3] << 16);
        o.z = el[4] | (el[5] << 16);
        o.w = el[6] | (el[7] << 16);
        ((uint4*)(hist + ex * BLOCK))[lane] = o;
        if (lane == 31) s_lbase[ex] = inc;   // row total (temp)
    }
    __syncthreads();

    // warp 0: block-local expert bases + delta vs scanned global offsets
    if (warp == 0) {
        uint32_t t0 = s_lbase[lane];
        uint32_t t1 = s_lbase[lane + 32];
        uint32_t i0 = warp_incl_scan(t0, lane);
        uint32_t tot0 = __shfl_sync(0xffffffffu, i0, 31);
        uint32_t e0 = i0 - t0;
        uint32_t i1 = warp_incl_scan(t1, lane);
        uint32_t e1 = i1 - t1 + tot0;
        uint32_t gb0 = g_counts[(size_t)lane * B + b];
        uint32_t gb1 = g_counts[(size_t)(lane + 32) * B + b];
        s_lbase[lane]       = e0;
        s_lbase[lane + 32]  = e1;
        s_delta[lane]       = (int)gb0 - (int)e0;
        s_delta[lane + 32]  = (int)gb1 - (int)e1;
    }
    __syncthreads();

    // --- Phase C: per-item local positions into registers (u16-packed) ---
    uint32_t p16[ITEMS / 2];
#pragma unroll
    for (int i = 0; i < ITEMS; i++) {
        uint32_t r = (i < 8) ? ((rn0 >> (4 * i)) & 0xFu)
                             : ((rn1 >> (4 * (i - 8))) & 0xFu);
        uint32_t p = s_lbase[e[i]] + (uint32_t)hist[e[i] * BLOCK + t] + r;
        if (i & 1) p16[i >> 1] |= p << 16;
        else       p16[i >> 1]  = p;
    }
    __syncthreads();   // all hist reads done -> safe to overlay

    // --- Phase D: stage scores + packed meta into sorted order ---
    {
        const float4* sp = (const float4*)(scores + (size_t)b * CHUNK + t * ITEMS);
#pragma unroll
        for (int v = 0; v < 4; v++) {
            float4 x = sp[v];
            float vv[4] = { x.x, x.y, x.z, x.w };
#pragma unroll
            for (int j = 0; j < 4; j++) {
                int i = 4 * v + j;
                uint32_t p = (p16[i >> 1] >> ((i & 1) * 16)) & 0xFFFFu;
                s_val[p]  = vv[j];
                s_meta[p] = (uint32_t)(t * ITEMS + i) | ((uint32_t)e[i] << 12);
            }
        }
    }
    __syncthreads();

    // --- Phase E: coalesced emit ---
    const int chunk_base = b * CHUNK;
#pragma unroll
    for (int i = 0; i < ITEMS; i++) {
        int p = t + i * BLOCK;
        float v = s_val[p];
        uint32_t m = s_meta[p];
        int li = (int)(m & 0xFFFu);
        int ei = (int)(m >> 12);
        int gp = p + s_delta[ei];
        out_scores[gp] = v;
        out_idx[gp]    = (float)(chunk_base + li);
    }
}

// ---------------------------------------------------------------------------
extern "C" void kernel_launch(void* const* d_in, const int* in_sizes, int n_in,
                              void* d_out, int out_size) {
    const float* scores  = (const float*)d_in[0];
    const int*   experts = (const int*)d_in[1];
    const int N = in_sizes[0];            // 8,388,608
    const int B = N / CHUNK;              // 2048

    float* out        = (float*)d_out;
    float* out_scores = out;
    float* out_idx    = out + N;
    float* out_counts = out + 2 * (size_t)N;

    k_zero<<<1, 64>>>();
    k_hist<<<B, BLOCK>>>(experts, B);
    k_scan<<<E, 256>>>(B, out_counts);
    k_scatter<<<B, BLOCK>>>(scores, experts, out_scores, out_idx, B);
}